// round 6
// baseline (speedup 1.0000x reference)
#include <cuda_runtime.h>

#define TILE    128
#define THREADS 512
#define INF     97      // real input features
#define INP     100     // padded X/W1 row stride (floats)
#define INP4    25      // float4 stride; 25 mod 8 odd -> LDS.128 conflict-free
#define MID     80
#define OUTD    64
#define HSTR    84      // H row stride; 21 float4, odd -> conflict-free
#define HSTR4   21
#define W2STR   80
#define W2STR4  20
#define OSTR    68      // output staging stride; 17 float4, odd -> conflict-free
#define OSTR4   17

__device__ __forceinline__ float2 ffma2(float2 a, float2 b, float2 c) {
    unsigned long long au = *reinterpret_cast<unsigned long long*>(&a);
    unsigned long long bu = *reinterpret_cast<unsigned long long*>(&b);
    unsigned long long cu = *reinterpret_cast<unsigned long long*>(&c);
    asm("fma.rn.f32x2 %0, %1, %2, %0;" : "+l"(cu) : "l"(au), "l"(bu));
    return *reinterpret_cast<float2*>(&cu);
}

__device__ __forceinline__ float fast_tanh(float x) {
    float e = __expf(2.0f * x);
    return 1.0f - __fdividef(2.0f, e + 1.0f);
}

extern __shared__ float smem[];

__global__ void __launch_bounds__(THREADS, 1)
edge_mlp_kernel(const float* __restrict__ dstf, const float* __restrict__ dsth,
                const float* __restrict__ srcf, const float* __restrict__ srch,
                const float* __restrict__ ef,
                const float* __restrict__ W1, const float* __restrict__ b1,
                const float* __restrict__ W2, const float* __restrict__ b2,
                float* __restrict__ out, int E)
{
    float* Xs  = smem;                    // TILE*INP (reused as output staging)
    float* Hs  = Xs  + TILE * INP;        // TILE*HSTR
    float* W1s = Hs  + TILE * HSTR;       // MID*INP
    float* W2s = W1s + MID * INP;         // OUTD*W2STR
    float* b1s = W2s + OUTD * W2STR;      // MID
    float* b2s = b1s + MID;               // OUTD

    const int tid  = threadIdx.x;
    const int lane = tid & 31;
    const int warp = tid >> 5;            // 0..15
    const int mg   = warp & 7;            // m/o group (8 groups)
    const int eb   = (warp >> 3) * 64;    // edge half base (2 halves)
    const int r0   = eb + lane;
    const int r1   = eb + lane + 32;

    // ---- stage weights once per (persistent) block ----
    for (int i = tid; i < MID * INF; i += THREADS) {
        int m = i / INF, k = i - m * INF;
        W1s[m * INP + k] = W1[i];
    }
    for (int i = tid; i < MID * 3; i += THREADS)      // zero pad cols 97..99
        W1s[(i / 3) * INP + 97 + (i % 3)] = 0.0f;
    for (int i = tid; i < OUTD * MID; i += THREADS) W2s[i] = W2[i];
    for (int i = tid; i < MID;  i += THREADS) b1s[i] = b1[i];
    for (int i = tid; i < OUTD; i += THREADS) b2s[i] = b2[i];
    __syncthreads();

    const int ntiles = (E + TILE - 1) / TILE;

    for (int tile = blockIdx.x; tile < ntiles; tile += gridDim.x) {
        const int e0  = tile * TILE;
        int rem = E - e0; if (rem > TILE) rem = TILE;

        // ---- stage X tile (float4 idx): dstf->0..3 | dsth->4..11 | srcf->12..15 |
        //                                 srch->16..23 | {ef,0,0,0}->24 ----
        {
            const float4* s0 = (const float4*)(dstf + (size_t)e0 * 16);
            const float4* s1 = (const float4*)(dsth + (size_t)e0 * 32);
            const float4* s2 = (const float4*)(srcf + (size_t)e0 * 16);
            const float4* s3 = (const float4*)(srch + (size_t)e0 * 32);
            float4* X4 = (float4*)Xs;  // row stride INP4=25
            for (int i = tid; i < TILE * 4; i += THREADS) {
                int r = i >> 2, c = i & 3;
                if (r < rem) X4[r * INP4 + c] = s0[r * 4 + c];
            }
            for (int i = tid; i < TILE * 8; i += THREADS) {
                int r = i >> 3, c = i & 7;
                if (r < rem) X4[r * INP4 + 4 + c] = s1[r * 8 + c];
            }
            for (int i = tid; i < TILE * 4; i += THREADS) {
                int r = i >> 2, c = i & 3;
                if (r < rem) X4[r * INP4 + 12 + c] = s2[r * 4 + c];
            }
            for (int i = tid; i < TILE * 8; i += THREADS) {
                int r = i >> 3, c = i & 7;
                if (r < rem) X4[r * INP4 + 16 + c] = s3[r * 8 + c];
            }
            for (int r = tid; r < TILE; r += THREADS)
                X4[r * INP4 + 24] = make_float4(r < rem ? ef[e0 + r] : 0.0f, 0.f, 0.f, 0.f);
        }
        __syncthreads();

        // ---- phase A: H = relu(X @ W1^T + b1); warp -> 10 m x 64 edges (2 rows/lane) ----
        {
            const float4* X4  = (const float4*)Xs;
            const float4* W14 = (const float4*)W1s;
            const int m0 = mg * 10;
            float2 acc[2][10];
            #pragma unroll
            for (int r = 0; r < 2; r++)
                #pragma unroll
                for (int j = 0; j < 10; j++) acc[r][j] = make_float2(0.f, 0.f);

            #pragma unroll
            for (int it = 0; it < INP4; ++it) {
                float4 x0 = X4[r0 * INP4 + it];
                float4 x1 = X4[r1 * INP4 + it];
                #pragma unroll
                for (int j = 0; j < 10; j++) {
                    float4 w = W14[(m0 + j) * INP4 + it];   // warp-uniform broadcast
                    acc[0][j] = ffma2(make_float2(x0.x, x0.y), make_float2(w.x, w.y), acc[0][j]);
                    acc[0][j] = ffma2(make_float2(x0.z, x0.w), make_float2(w.z, w.w), acc[0][j]);
                    acc[1][j] = ffma2(make_float2(x1.x, x1.y), make_float2(w.x, w.y), acc[1][j]);
                    acc[1][j] = ffma2(make_float2(x1.z, x1.w), make_float2(w.z, w.w), acc[1][j]);
                }
            }
            #pragma unroll
            for (int j = 0; j < 10; j++) {
                float bb = b1s[m0 + j];
                float sa = acc[0][j].x + acc[0][j].y + bb;
                float sb = acc[1][j].x + acc[1][j].y + bb;
                Hs[r0 * HSTR + m0 + j] = fmaxf(sa, 0.0f);
                Hs[r1 * HSTR + m0 + j] = fmaxf(sb, 0.0f);
            }
        }
        __syncthreads();

        // ---- phase B: O = tanh(H @ W2^T + b2); warp -> 8 o x 64 edges ----
        {
            const float4* H4  = (const float4*)Hs;
            const float4* W24 = (const float4*)W2s;
            float* Ot = Xs;                          // reuse X buffer, stride OSTR
            const int o0 = mg * 8;
            float2 acc[2][8];
            #pragma unroll
            for (int r = 0; r < 2; r++)
                #pragma unroll
                for (int j = 0; j < 8; j++) acc[r][j] = make_float2(0.f, 0.f);

            #pragma unroll
            for (int it = 0; it < W2STR4; ++it) {
                float4 h0 = H4[r0 * HSTR4 + it];
                float4 h1 = H4[r1 * HSTR4 + it];
                #pragma unroll
                for (int j = 0; j < 8; j++) {
                    float4 w = W24[(o0 + j) * W2STR4 + it];  // warp-uniform broadcast
                    acc[0][j] = ffma2(make_float2(h0.x, h0.y), make_float2(w.x, w.y), acc[0][j]);
                    acc[0][j] = ffma2(make_float2(h0.z, h0.w), make_float2(w.z, w.w), acc[0][j]);
                    acc[1][j] = ffma2(make_float2(h1.x, h1.y), make_float2(w.x, w.y), acc[1][j]);
                    acc[1][j] = ffma2(make_float2(h1.z, h1.w), make_float2(w.z, w.w), acc[1][j]);
                }
            }
            #pragma unroll
            for (int j = 0; j < 8; j++) {
                float bb = b2s[o0 + j];
                float sa = acc[0][j].x + acc[0][j].y + bb;
                float sb = acc[1][j].x + acc[1][j].y + bb;
                Ot[r0 * OSTR + o0 + j] = fast_tanh(sa);
                Ot[r1 * OSTR + o0 + j] = fast_tanh(sb);
            }
        }
        __syncthreads();

        // ---- coalesced float4 write-out ----
        {
            const float4* O4 = (const float4*)Xs;    // stride OSTR4=17
            float4* outp = (float4*)(out + (size_t)e0 * OUTD);
            for (int i = tid; i < TILE * 16; i += THREADS) {
                int r = i >> 4, c = i & 15;
                if (r < rem) outp[r * 16 + c] = O4[r * OSTR4 + c];
            }
        }
        __syncthreads();  // protect Xs before next tile's staging
    }
}

extern "C" void kernel_launch(void* const* d_in, const int* in_sizes, int n_in,
                              void* d_out, int out_size) {
    const float* dstf = (const float*)d_in[0];
    const float* dsth = (const float*)d_in[1];
    const float* srcf = (const float*)d_in[2];
    const float* srch = (const float*)d_in[3];
    const float* ef   = (const float*)d_in[4];
    const float* W1   = (const float*)d_in[5];
    const float* b1   = (const float*)d_in[6];
    const float* W2   = (const float*)d_in[7];
    const float* b2   = (const float*)d_in[8];
    float* out = (float*)d_out;
    const int E = in_sizes[4];
    (void)n_in; (void)out_size;

    const int smem_bytes = (TILE * INP + TILE * HSTR + MID * INP +
                            OUTD * W2STR + MID + OUTD) * (int)sizeof(float);  // ~147 KB

    cudaFuncSetAttribute(edge_mlp_kernel,
                         cudaFuncAttributeMaxDynamicSharedMemorySize, smem_bytes);

    int sms = 148;
    cudaDeviceGetAttribute(&sms, cudaDevAttrMultiProcessorCount, 0);

    edge_mlp_kernel<<<sms, THREADS, smem_bytes>>>(
        dstf, dsth, srcf, srch, ef, W1, b1, W2, b2, out, E);
}

// round 7
// speedup vs baseline: 2.1541x; 2.1541x over previous
#include <cuda_runtime.h>
#include <cuda_bf16.h>
#include <cstdint>

#define THREADS 512
#define TILE    128

// bf16 tiles, row stride in BYTES (odd multiples of 16B -> conflict-free LDSM)
#define ASTR1 464   // A1: 128 x [xhi(112) | xlo(112)] halves, 232 halves padded
#define BSTR1 464   // B1: 80  x [whi(112) | wlo(112)]
#define ASTR2 336   // A2: 128 x [hhi(80)  | hlo(80)]  halves, 168 padded
#define BSTR2 336   // B2: 64  x [whi(80)  | wlo(80)]

#define OFF_A1  0         // 128*464 = 59392
#define OFF_A2  59392     // 128*336 = 43008 -> 102400
#define OFF_B1  102400    // 80*464  = 37120 -> 139520
#define OFF_B2  139520    // 64*336  = 21504 -> 161024
#define OFF_B1S 161024    // 80 f32
#define OFF_B2S 161344    // 64 f32
#define SMEM_TOTAL 161664

__device__ __forceinline__ uint32_t smem_u32(const void* p) {
    uint32_t a;
    asm("{ .reg .u64 t; cvta.to.shared.u64 t, %1; cvt.u32.u64 %0, t; }" : "=r"(a) : "l"(p));
    return a;
}

// split fp32 pair -> packed bf16x2 (hi) + packed bf16x2 (lo residual)
__device__ __forceinline__ void split_pack(float x0, float x1, uint32_t& hi, uint32_t& lo) {
    uint16_t h0 = __bfloat16_as_ushort(__float2bfloat16_rn(x0));
    uint16_t h1 = __bfloat16_as_ushort(__float2bfloat16_rn(x1));
    float f0 = __uint_as_float((uint32_t)h0 << 16);
    float f1 = __uint_as_float((uint32_t)h1 << 16);
    uint16_t l0 = __bfloat16_as_ushort(__float2bfloat16_rn(x0 - f0));
    uint16_t l1 = __bfloat16_as_ushort(__float2bfloat16_rn(x1 - f1));
    hi = (uint32_t)h0 | ((uint32_t)h1 << 16);
    lo = (uint32_t)l0 | ((uint32_t)l1 << 16);
}

__device__ __forceinline__ float fast_tanh(float x) {
    float e = __expf(2.0f * x);
    return 1.0f - __fdividef(2.0f, e + 1.0f);
}

__device__ __forceinline__ void ldsm_x4(uint32_t& r0, uint32_t& r1, uint32_t& r2, uint32_t& r3,
                                        uint32_t addr) {
    asm volatile("ldmatrix.sync.aligned.m8n8.x4.shared.b16 {%0,%1,%2,%3}, [%4];"
        : "=r"(r0), "=r"(r1), "=r"(r2), "=r"(r3) : "r"(addr));
}
__device__ __forceinline__ void ldsm_x2(uint32_t& r0, uint32_t& r1, uint32_t addr) {
    asm volatile("ldmatrix.sync.aligned.m8n8.x2.shared.b16 {%0,%1}, [%2];"
        : "=r"(r0), "=r"(r1) : "r"(addr));
}

__device__ __forceinline__ void mma16816(float* d, uint32_t a0, uint32_t a1, uint32_t a2,
                                         uint32_t a3, uint32_t b0, uint32_t b1) {
    asm volatile(
        "mma.sync.aligned.m16n8k16.row.col.f32.bf16.bf16.f32 "
        "{%0,%1,%2,%3}, {%4,%5,%6,%7}, {%8,%9}, {%0,%1,%2,%3};"
        : "+f"(d[0]), "+f"(d[1]), "+f"(d[2]), "+f"(d[3])
        : "r"(a0), "r"(a1), "r"(a2), "r"(a3), "r"(b0), "r"(b1));
}

extern __shared__ char smem[];

__global__ void __launch_bounds__(THREADS, 1)
edge_mlp_mma(const float* __restrict__ dstf, const float* __restrict__ dsth,
             const float* __restrict__ srcf, const float* __restrict__ srch,
             const float* __restrict__ ef,
             const float* __restrict__ W1, const float* __restrict__ b1,
             const float* __restrict__ W2, const float* __restrict__ b2,
             float* __restrict__ out, int E)
{
    const uint32_t sb = smem_u32(smem);
    const int tid  = threadIdx.x;
    const int lane = tid & 31;
    const int warp = tid >> 5;            // 0..15
    float* b1s = (float*)(smem + OFF_B1S);
    float* b2s = (float*)(smem + OFF_B2S);

    // ---- one-time zero (covers all k-pads) ----
    for (int i = tid; i < OFF_B1S / 4; i += THREADS) ((uint32_t*)smem)[i] = 0u;
    __syncthreads();

    // ---- stage split weights ----
    for (int i = tid; i < 80 * 56; i += THREADS) {        // W1: 56 k-pairs/row
        int n = i / 56, c2 = (i - n * 56) * 2;            // c2 = 0..110 even
        float w0 = (c2     < 97) ? W1[n * 97 + c2]     : 0.0f;
        float w1 = (c2 + 1 < 97) ? W1[n * 97 + c2 + 1] : 0.0f;
        uint32_t hi, lo; split_pack(w0, w1, hi, lo);
        *(uint32_t*)(smem + OFF_B1 + n * BSTR1 + c2 * 2)         = hi;
        *(uint32_t*)(smem + OFF_B1 + n * BSTR1 + (112 + c2) * 2) = lo;
    }
    for (int i = tid; i < 64 * 40; i += THREADS) {        // W2: 40 k-pairs/row
        int n = i / 40, c2 = (i - n * 40) * 2;            // c2 = 0..78 even
        float w0 = W2[n * 80 + c2], w1 = W2[n * 80 + c2 + 1];
        uint32_t hi, lo; split_pack(w0, w1, hi, lo);
        *(uint32_t*)(smem + OFF_B2 + n * BSTR2 + c2 * 2)        = hi;
        *(uint32_t*)(smem + OFF_B2 + n * BSTR2 + (80 + c2) * 2) = lo;
    }
    if (tid < 80) b1s[tid] = b1[tid];
    if (tid < 64) b2s[tid] = b2[tid];
    __syncthreads();

    const int mrow  = (warp & 7) * 16;    // 8 row-groups of 16
    const int ncolA = (warp >> 3) * 40;   // 2 col-groups: phase A n40
    const int ncolB = (warp >> 3) * 32;   // phase B n32
    const int rA = (lane >> 2);           // frag row within m16 (0..7); rB = rA+8
    const int cc = 2 * (lane & 3);        // frag col pair base within n8

    // ldmatrix lane-address components
    const int aRow = lane & 15;           // A: rows mrow..mrow+15
    const int aKof = (lane >> 4) * 8;     // A: k offset 0/8
    const int bRow = lane & 7;            // B: rows nb..nb+7 (lanes 0..15 used)
    const int bKof = ((lane >> 3) & 1) * 8;

    const int ntiles = (E + TILE - 1) / TILE;

    for (int tile = blockIdx.x; tile < ntiles; tile += gridDim.x) {
        const int e0 = tile * TILE;
        int rem = E - e0; if (rem > TILE) rem = TILE;

        // ---- stage A1: gather + split; f4 chunk covers k0..k0+3 ----
        for (int i = tid; i < TILE * 25; i += THREADS) {
            int r = i / 25;
            if (r >= rem) continue;
            int k0 = (i - r * 25) * 4;    // 0..96
            size_t ge = (size_t)(e0 + r);
            float4 x;
            if      (k0 < 16) x = *(const float4*)(dstf + ge * 16 + k0);
            else if (k0 < 48) x = *(const float4*)(dsth + ge * 32 + (k0 - 16));
            else if (k0 < 64) x = *(const float4*)(srcf + ge * 16 + (k0 - 48));
            else if (k0 < 96) x = *(const float4*)(srch + ge * 32 + (k0 - 64));
            else              x = make_float4(ef[ge], 0.0f, 0.0f, 0.0f);
            uint32_t h0, l0, h1, l1;
            split_pack(x.x, x.y, h0, l0);
            split_pack(x.z, x.w, h1, l1);
            char* rp = smem + OFF_A1 + r * ASTR1;
            *(uint32_t*)(rp + k0 * 2)           = h0;
            *(uint32_t*)(rp + k0 * 2 + 4)       = h1;
            *(uint32_t*)(rp + (112 + k0) * 2)     = l0;
            *(uint32_t*)(rp + (112 + k0) * 2 + 4) = l1;
        }
        __syncthreads();

        // ---- phase A: H[128x80] += 3-term split GEMM, 21 k-steps ----
        float acc[5][4];
        #pragma unroll
        for (int j = 0; j < 5; j++)
            #pragma unroll
            for (int q = 0; q < 4; q++) acc[j][q] = 0.0f;

        {
            const uint32_t aBase = sb + OFF_A1 + (mrow + aRow) * ASTR1 + aKof * 2;
            uint32_t bBase[5];
            #pragma unroll
            for (int j = 0; j < 5; j++)
                bBase[j] = sb + OFF_B1 + (ncolA + 8 * j + bRow) * BSTR1 + bKof * 2;

            #pragma unroll
            for (int s = 0; s < 21; s++) {
                const int t  = (s < 7) ? 0 : ((s < 14) ? 1 : 2);
                const int sk = s - ((t == 1) ? 7 : ((t == 2) ? 14 : 0));
                const int kA = ((t == 1) ? 112 : 0) + sk * 16;
                const int kB = ((t == 2) ? 112 : 0) + sk * 16;
                uint32_t a0, a1, a2, a3;
                ldsm_x4(a0, a1, a2, a3, aBase + kA * 2);
                #pragma unroll
                for (int j = 0; j < 5; j++) {
                    uint32_t b0v, b1v;
                    ldsm_x2(b0v, b1v, bBase[j] + kB * 2);
                    mma16816(acc[j], a0, a1, a2, a3, b0v, b1v);
                }
            }
        }
        __syncthreads();   // all A2 readers (prev phase B) done & before A2 writers race readers

        // ---- epilogue A: relu(+b1), split -> A2 ----
        #pragma unroll
        for (int j = 0; j < 5; j++) {
            const int c0 = ncolA + 8 * j + cc;
            const float bb0 = b1s[c0], bb1 = b1s[c0 + 1];
            float h00 = fmaxf(acc[j][0] + bb0, 0.0f), h01 = fmaxf(acc[j][1] + bb1, 0.0f);
            float h10 = fmaxf(acc[j][2] + bb0, 0.0f), h11 = fmaxf(acc[j][3] + bb1, 0.0f);
            uint32_t hi, lo;
            char* rp0 = smem + OFF_A2 + (mrow + rA) * ASTR2;
            char* rp1 = smem + OFF_A2 + (mrow + rA + 8) * ASTR2;
            split_pack(h00, h01, hi, lo);
            *(uint32_t*)(rp0 + c0 * 2) = hi;  *(uint32_t*)(rp0 + (80 + c0) * 2) = lo;
            split_pack(h10, h11, hi, lo);
            *(uint32_t*)(rp1 + c0 * 2) = hi;  *(uint32_t*)(rp1 + (80 + c0) * 2) = lo;
        }
        __syncthreads();   // A2 complete before phase B reads

        // ---- phase B: O[128x64], 15 k-steps ----
        float acc2[4][4];
        #pragma unroll
        for (int j = 0; j < 4; j++)
            #pragma unroll
            for (int q = 0; q < 4; q++) acc2[j][q] = 0.0f;

        {
            const uint32_t aBase = sb + OFF_A2 + (mrow + aRow) * ASTR2 + aKof * 2;
            uint32_t bBase[4];
            #pragma unroll
            for (int j = 0; j < 4; j++)
                bBase[j] = sb + OFF_B2 + (ncolB + 8 * j + bRow) * BSTR2 + bKof * 2;

            #pragma unroll
            for (int s = 0; s < 15; s++) {
                const int t  = (s < 5) ? 0 : ((s < 10) ? 1 : 2);
                const int sk = s - ((t == 1) ? 5 : ((t == 2) ? 10 : 0));
                const int kA = ((t == 1) ? 80 : 0) + sk * 16;
                const int kB = ((t == 2) ? 80 : 0) + sk * 16;
                uint32_t a0, a1, a2, a3;
                ldsm_x4(a0, a1, a2, a3, aBase + kA * 2);
                #pragma unroll
                for (int j = 0; j < 4; j++) {
                    uint32_t b0v, b1v;
                    ldsm_x2(b0v, b1v, bBase[j] + kB * 2);
                    mma16816(acc2[j], a0, a1, a2, a3, b0v, b1v);
                }
            }
        }

        // ---- epilogue B: tanh(+b2) -> direct coalesced-ish STG.64 ----
        {
            const int gr0 = e0 + mrow + rA;
            const int gr1 = gr0 + 8;
            #pragma unroll
            for (int j = 0; j < 4; j++) {
                const int c0 = ncolB + 8 * j + cc;
                const float bb0 = b2s[c0], bb1 = b2s[c0 + 1];
                if (gr0 < E) {
                    float2 v = make_float2(fast_tanh(acc2[j][0] + bb0),
                                           fast_tanh(acc2[j][1] + bb1));
                    *(float2*)(out + (size_t)gr0 * 64 + c0) = v;
                }
                if (gr1 < E) {
                    float2 v = make_float2(fast_tanh(acc2[j][2] + bb0),
                                           fast_tanh(acc2[j][3] + bb1));
                    *(float2*)(out + (size_t)gr1 * 64 + c0) = v;
                }
            }
        }
        // no barrier: next-tile A1 staging is disjoint from A2/B2 reads;
        // phase-A mma of next tile is gated by the post-staging barrier.
    }
}

extern "C" void kernel_launch(void* const* d_in, const int* in_sizes, int n_in,
                              void* d_out, int out_size) {
    const float* dstf = (const float*)d_in[0];
    const float* dsth = (const float*)d_in[1];
    const float* srcf = (const float*)d_in[2];
    const float* srch = (const float*)d_in[3];
    const float* ef   = (const float*)d_in[4];
    const float* W1   = (const float*)d_in[5];
    const float* b1   = (const float*)d_in[6];
    const float* W2   = (const float*)d_in[7];
    const float* b2   = (const float*)d_in[8];
    float* out = (float*)d_out;
    const int E = in_sizes[4];
    (void)n_in; (void)out_size;

    cudaFuncSetAttribute(edge_mlp_mma,
                         cudaFuncAttributeMaxDynamicSharedMemorySize, SMEM_TOTAL);
    int sms = 148;
    cudaDeviceGetAttribute(&sms, cudaDevAttrMultiProcessorCount, 0);

    edge_mlp_mma<<<sms, THREADS, SMEM_TOTAL>>>(
        dstf, dsth, srcf, srch, ef, W1, b1, W2, b2, out, E);
}